// round 11
// baseline (speedup 1.0000x reference)
#include <cuda_runtime.h>
#include <cuda_bf16.h>
#include <math_constants.h>

// CropSplitGT: out[h, w, n] = data[h, w, n] if (w,h) inside roi box n else 0.
// data (H, W, N) row-major, rois (4, N) = [x1; y1; x2; y2].
//
// Persistent grid-stride version of the round-10 kernel:
//  - 592 resident-ish CTAs loop over 12800 tiles in x-major order (the
//    traversal order proven best in rounds 8-9), amortizing block prologue
//    and wave-transition overhead.
//  - per-component row-interval -> packed 32-bit mask (1 reg)
//  - 8 predicated ld.global.cs.v4, immediate row offsets (MLP 8)
//  - dense .cs stores, all 32-bit offsets.

#define HH 512
#define WW 512
#define NN 400
#define N4 (NN / 4)            // 100 float4 per pixel
#define ROW4 (WW * N4)         // 51200 float4 per row
#define ROWB 819200            // row stride in BYTES
#define H_PER 8
#define GY (HH / H_PER)        // 64 bands
#define TPB 256
#define GX (ROW4 / TPB)        // 200 x-blocks
#define TILES (GX * GY)        // 12800
#define NBLOCKS 592            // ~4 blocks/SM worth of persistent CTAs

// Predicated 128-bit streaming load at [base + literal byte offset].
// Contents UNDEFINED when pred==0; caller's blend masks them.
#define LDG_CS_PRED_OFF(dst, pred, base, I)                              \
    asm("{\n\t"                                                          \
        ".reg .pred %%pp;\n\t"                                           \
        "setp.ne.u32 %%pp, %4, 0;\n\t"                                   \
        "@%%pp ld.global.cs.v4.f32 {%0, %1, %2, %3}, [%5 + %6];\n\t"     \
        "}"                                                              \
        : "=f"((dst).x), "=f"((dst).y), "=f"((dst).z), "=f"((dst).w)     \
        : "r"(pred), "l"(base), "n"((I) * (long)ROWB))

// 8-bit mask of rows i in [0,8) with (h0+i) in [y1, y2] (inclusive).
// y1 == +inf (x-miss fold) yields 0. Clamps keep shifts in [0,8].
__device__ __forceinline__ unsigned row_mask(float y1, float y2, float h0f)
{
    int ilo = __float2int_ru(y1 - h0f);   // saturates on +inf
    int ihi = __float2int_rd(y2 - h0f);
    ilo = max(ilo, 0);  ilo = min(ilo, 8);
    ihi = min(ihi, 7);  ihi = max(ihi, -1);
    return ((1u << (ihi + 1)) - 1u) & ~((1u << ilo) - 1u);
}

__global__ __launch_bounds__(TPB) void crop_split_gt_kernel(
    const float4* __restrict__ data,
    const float*  __restrict__ rois,
    float4*       __restrict__ out)
{
    for (unsigned t = blockIdx.x; t < TILES; t += NBLOCKS) {
        // x-major order: consecutive t = consecutive x-blocks within a band.
        const unsigned band = t / GX;
        const unsigned xblk = t - band * GX;

        const unsigned tid = xblk * TPB + threadIdx.x;   // [0, ROW4)
        const unsigned w   = tid / N4;
        const unsigned n4  = tid - w * N4;
        const float wf = (float)w;

        const float4 x1 = __ldg((const float4*)(rois)          + n4);
        const float4 x2 = __ldg((const float4*)(rois + 2 * NN) + n4);
        float4 y1 = __ldg((const float4*)(rois + NN)     + n4);
        float4 y2 = __ldg((const float4*)(rois + 3 * NN) + n4);

        // Fold x-mask into y-range: outside [x1,x2] -> empty interval.
        if (!(wf >= x1.x && wf <= x2.x)) y1.x = CUDART_INF_F;
        if (!(wf >= x1.y && wf <= x2.y)) y1.y = CUDART_INF_F;
        if (!(wf >= x1.z && wf <= x2.z)) y1.z = CUDART_INF_F;
        if (!(wf >= x1.w && wf <= x2.w)) y1.w = CUDART_INF_F;

        const unsigned h0 = band * H_PER;
        const float h0f = (float)h0;

        // All 32 mask bits in one register: byte c = rows of component c.
        const unsigned m0 = row_mask(y1.x, y2.x, h0f);
        const unsigned m1 = row_mask(y1.y, y2.y, h0f);
        const unsigned m2 = row_mask(y1.z, y2.z, h0f);
        const unsigned m3 = row_mask(y1.w, y2.w, h0f);
        const unsigned mpack = m0 | (m1 << 8) | (m2 << 16) | (m3 << 24);
        const unsigned anyb  = m0 | m1 | m2 | m3;

        const unsigned base = h0 * (unsigned)ROW4 + tid;   // < 2^25
        const float4* __restrict__ pbase = data + base;

        // 8 predicated loads in flight (imm offsets, one base reg).
        float4 v[H_PER];
        LDG_CS_PRED_OFF(v[0], anyb & 0x01u, pbase, 0);
        LDG_CS_PRED_OFF(v[1], anyb & 0x02u, pbase, 1);
        LDG_CS_PRED_OFF(v[2], anyb & 0x04u, pbase, 2);
        LDG_CS_PRED_OFF(v[3], anyb & 0x08u, pbase, 3);
        LDG_CS_PRED_OFF(v[4], anyb & 0x10u, pbase, 4);
        LDG_CS_PRED_OFF(v[5], anyb & 0x20u, pbase, 5);
        LDG_CS_PRED_OFF(v[6], anyb & 0x40u, pbase, 6);
        LDG_CS_PRED_OFF(v[7], anyb & 0x80u, pbase, 7);

        // Blend from mpack bits + dense stores.
        float4* __restrict__ obase = out + base;
        #pragma unroll
        for (int i = 0; i < H_PER; ++i) {
            const unsigned tb = mpack >> i;
            float4 r;
            r.x = (tb & 0x00000001u) ? v[i].x : 0.0f;
            r.y = (tb & 0x00000100u) ? v[i].y : 0.0f;
            r.z = (tb & 0x00010000u) ? v[i].z : 0.0f;
            r.w = (tb & 0x01000000u) ? v[i].w : 0.0f;
            __stcs(obase + (unsigned)(i * ROW4), r);
        }
    }
}

extern "C" void kernel_launch(void* const* d_in, const int* in_sizes, int n_in,
                              void* d_out, int out_size)
{
    const float4* data = (const float4*)d_in[0];
    const float*  rois = (const float*)d_in[1];
    float4* out = (float4*)d_out;

    crop_split_gt_kernel<<<NBLOCKS, TPB>>>(data, rois, out);
}

// round 12
// speedup vs baseline: 1.1713x; 1.1713x over previous
#include <cuda_runtime.h>
#include <cuda_bf16.h>
#include <math_constants.h>

// CropSplitGT: out[h, w, n] = data[h, w, n] if (w,h) inside roi box n else 0.
// data (H, W, N) row-major, rois (4, N) = [x1; y1; x2; y2].
//
// Champion structure (round 10) with TPB 512:
//  - 2D x-major grid (proven best DRAM locality; band-interleave and
//    persistent variants both regressed)
//  - per-component row-interval -> packed 32-bit mask in ONE register
//  - 8 predicated ld.global.cs.v4 with immediate row offsets (MLP 8)
//  - dense .cs stores, all 32-bit offsets.

#define HH 512
#define WW 512
#define NN 400
#define N4 (NN / 4)            // 100 float4 per pixel
#define ROW4 (WW * N4)         // 51200 float4 per row
#define ROWB 819200            // row stride in BYTES
#define H_PER 8
#define GY (HH / H_PER)        // 64 bands
#define TPB 512
#define GX (ROW4 / TPB)        // 100 x-blocks

// Predicated 128-bit streaming load at [base + literal byte offset].
// Contents UNDEFINED when pred==0; caller's blend masks them.
#define LDG_CS_PRED_OFF(dst, pred, base, I)                              \
    asm("{\n\t"                                                          \
        ".reg .pred %%pp;\n\t"                                           \
        "setp.ne.u32 %%pp, %4, 0;\n\t"                                   \
        "@%%pp ld.global.cs.v4.f32 {%0, %1, %2, %3}, [%5 + %6];\n\t"     \
        "}"                                                              \
        : "=f"((dst).x), "=f"((dst).y), "=f"((dst).z), "=f"((dst).w)     \
        : "r"(pred), "l"(base), "n"((I) * (long)ROWB))

// 8-bit mask of rows i in [0,8) with (h0+i) in [y1, y2] (inclusive).
// y1 == +inf (x-miss fold) yields 0. Clamps keep shifts in [0,8].
__device__ __forceinline__ unsigned row_mask(float y1, float y2, float h0f)
{
    int ilo = __float2int_ru(y1 - h0f);   // saturates on +inf
    int ihi = __float2int_rd(y2 - h0f);
    ilo = max(ilo, 0);  ilo = min(ilo, 8);
    ihi = min(ihi, 7);  ihi = max(ihi, -1);
    return ((1u << (ihi + 1)) - 1u) & ~((1u << ilo) - 1u);
}

__global__ __launch_bounds__(TPB) void crop_split_gt_kernel(
    const float4* __restrict__ data,
    const float*  __restrict__ rois,
    float4*       __restrict__ out)
{
    const unsigned tid = blockIdx.x * TPB + threadIdx.x;   // [0, ROW4)
    const unsigned w   = tid / N4;
    const unsigned n4  = tid - w * N4;
    const float wf = (float)w;

    const float4 x1 = __ldg((const float4*)(rois)          + n4);
    const float4 x2 = __ldg((const float4*)(rois + 2 * NN) + n4);
    float4 y1 = __ldg((const float4*)(rois + NN)     + n4);
    float4 y2 = __ldg((const float4*)(rois + 3 * NN) + n4);

    // Fold x-mask into y-range: outside [x1,x2] -> empty interval.
    if (!(wf >= x1.x && wf <= x2.x)) y1.x = CUDART_INF_F;
    if (!(wf >= x1.y && wf <= x2.y)) y1.y = CUDART_INF_F;
    if (!(wf >= x1.z && wf <= x2.z)) y1.z = CUDART_INF_F;
    if (!(wf >= x1.w && wf <= x2.w)) y1.w = CUDART_INF_F;

    const unsigned h0 = blockIdx.y * H_PER;
    const float h0f = (float)h0;

    // All 32 mask bits in one register: byte c = rows mask of component c.
    const unsigned m0 = row_mask(y1.x, y2.x, h0f);
    const unsigned m1 = row_mask(y1.y, y2.y, h0f);
    const unsigned m2 = row_mask(y1.z, y2.z, h0f);
    const unsigned m3 = row_mask(y1.w, y2.w, h0f);
    const unsigned mpack = m0 | (m1 << 8) | (m2 << 16) | (m3 << 24);
    const unsigned anyb  = m0 | m1 | m2 | m3;   // row i needs a read iff bit i

    // 32-bit element offset (max 26.2M < 2^31).
    const unsigned base = h0 * (unsigned)ROW4 + tid;
    const float4* __restrict__ pbase = data + base;

    // 8 predicated loads in flight (imm offsets, one base reg).
    float4 v[H_PER];
    LDG_CS_PRED_OFF(v[0], anyb & 0x01u, pbase, 0);
    LDG_CS_PRED_OFF(v[1], anyb & 0x02u, pbase, 1);
    LDG_CS_PRED_OFF(v[2], anyb & 0x04u, pbase, 2);
    LDG_CS_PRED_OFF(v[3], anyb & 0x08u, pbase, 3);
    LDG_CS_PRED_OFF(v[4], anyb & 0x10u, pbase, 4);
    LDG_CS_PRED_OFF(v[5], anyb & 0x20u, pbase, 5);
    LDG_CS_PRED_OFF(v[6], anyb & 0x40u, pbase, 6);
    LDG_CS_PRED_OFF(v[7], anyb & 0x80u, pbase, 7);

    // Blend from mpack bits + dense stores (32-bit offsets).
    float4* __restrict__ obase = out + base;
    #pragma unroll
    for (int i = 0; i < H_PER; ++i) {
        const unsigned t = mpack >> i;
        float4 r;
        r.x = (t & 0x00000001u) ? v[i].x : 0.0f;
        r.y = (t & 0x00000100u) ? v[i].y : 0.0f;
        r.z = (t & 0x00010000u) ? v[i].z : 0.0f;
        r.w = (t & 0x01000000u) ? v[i].w : 0.0f;
        __stcs(obase + (unsigned)(i * ROW4), r);
    }
}

extern "C" void kernel_launch(void* const* d_in, const int* in_sizes, int n_in,
                              void* d_out, int out_size)
{
    const float4* data = (const float4*)d_in[0];
    const float*  rois = (const float*)d_in[1];
    float4* out = (float4*)d_out;

    dim3 block(TPB);
    dim3 grid(GX, GY);   // 100 x 64 blocks, x-major
    crop_split_gt_kernel<<<grid, block>>>(data, rois, out);
}